// round 2
// baseline (speedup 1.0000x reference)
#include <cuda_runtime.h>

#define BATCH 4096
#define SEQ   200
#define EMB   128
#define VOCAB 100000

__global__ __launch_bounds__(128, 8)
void pool_linear_kernel(const int* __restrict__ x,
                        const float* __restrict__ emb,
                        const float* __restrict__ W,
                        const float* __restrict__ bias,
                        float* __restrict__ out)
{
    const int row  = blockIdx.x;
    const int tid  = threadIdx.x;
    const int warp = tid >> 5;
    const int lane = tid & 31;

    const int* xr = x + row * SEQ;

    float4 acc = make_float4(0.f, 0.f, 0.f, 0.f);
    int cnt = 0;

    // Each warp handles tokens s = warp, warp+4, ... ; 50 iterations.
    #pragma unroll 5
    for (int s = warp; s < SEQ; s += 4) {
        int idx = xr[s];                    // broadcast load (same addr all lanes)
        if (idx >= 0 && idx < VOCAB) {      // mask per reference; upper bound = fault guard
            const float4* e = reinterpret_cast<const float4*>(emb + (long long)idx * EMB);
            float4 v = __ldg(&e[lane]);     // coalesced 512B row load
            acc.x += v.x; acc.y += v.y; acc.z += v.z; acc.w += v.w;
            cnt++;
        }
    }

    // Cross-warp reduction of the 128-dim accumulator and the counts.
    __shared__ float  sacc[4][EMB];
    __shared__ int    scnt[4];

    reinterpret_cast<float4*>(sacc[warp])[lane] = acc;
    if (lane == 0) scnt[warp] = cnt;        // cnt uniform across lanes in warp
    __syncthreads();

    const int d = tid;                      // dim owned by this thread
    float total = sacc[0][d] + sacc[1][d] + sacc[2][d] + sacc[3][d];
    int   count = scnt[0] + scnt[1] + scnt[2] + scnt[3];
    float pooled = total * (1.0f / (float)count);   // count >= 1 guaranteed

    // Tiny linear: out[row][k] = sum_d pooled[d]*W[k][d] + b[k]
    __shared__ float red[2][EMB];
    red[0][d] = pooled * W[d];
    red[1][d] = pooled * W[EMB + d];
    __syncthreads();

    if (warp < 2) {
        float v = red[warp][lane] + red[warp][lane + 32]
                + red[warp][lane + 64] + red[warp][lane + 96];
        #pragma unroll
        for (int off = 16; off > 0; off >>= 1)
            v += __shfl_down_sync(0xFFFFFFFFu, v, off);
        if (lane == 0)
            out[row * 2 + warp] = v + bias[warp];
    }
}

extern "C" void kernel_launch(void* const* d_in, const int* in_sizes, int n_in,
                              void* d_out, int out_size)
{
    const int* x     = (const int*)d_in[0];       // int32 [4096,200] (JAX x64 off)
    const float* emb = (const float*)d_in[1];     // [100000,128]
    const float* W   = (const float*)d_in[2];     // [2,128]
    const float* b   = (const float*)d_in[3];     // [2]
    float* out       = (float*)d_out;             // [4096,2]

    pool_linear_kernel<<<BATCH, 128>>>(x, emb, W, b, out);
}